// round 12
// baseline (speedup 1.0000x reference)
#include <cuda_runtime.h>
#include <math.h>
#include <stdint.h>

#define TT   1024
#define DMM  1024
#define HH   16
#define RNK  32
#define NT   16
#define SCALE 0.125f
#define NPROJ 3120     // 3*1024 + 32 + 16

#define PA_  68
#define PB_  72
#define ASZ  (64*PA_)
#define BSZ  (64*PB_)

// ---------------- scratch (device globals) ----------------------------------
__device__ float g_q   [TT*DMM];
__device__ float g_k   [TT*DMM];
__device__ float g_v   [TT*DMM];
__device__ float g_wpre[TT*DMM];
__device__ float g_w   [TT*DMM];
__device__ float g_xw1 [TT*RNK];
__device__ float g_beta[TT*HH];
__device__ float g_invA[HH*NT*64*64];
__device__ float g_MkD [HH*NT*64*64]; // strict diag Mk blocks, NEGATED
__device__ float g_o [TT*DMM];

// ---------------- tf32 helpers ------------------------------------------------
__device__ __forceinline__ float to_tf32(float x) {
    uint32_t u; asm("cvt.rna.tf32.f32 %0, %1;" : "=r"(u) : "f"(x));
    return __uint_as_float(u);
}
__device__ __forceinline__ float4 tf4(float4 v) {
    v.x = to_tf32(v.x); v.y = to_tf32(v.y); v.z = to_tf32(v.z); v.w = to_tf32(v.w);
    return v;
}

__device__ __forceinline__ void mma8(float (&c)[4], const uint32_t (&a)[4],
                                     const uint32_t (&b)[2]) {
    asm volatile(
        "mma.sync.aligned.m16n8k8.row.col.f32.tf32.tf32.f32 "
        "{%0,%1,%2,%3},{%4,%5,%6,%7},{%8,%9},{%0,%1,%2,%3};"
        : "+f"(c[0]), "+f"(c[1]), "+f"(c[2]), "+f"(c[3])
        : "r"(a[0]), "r"(a[1]), "r"(a[2]), "r"(a[3]), "r"(b[0]), "r"(b[1]));
}

// ---- 8-warp layout (256 threads, warp tile 32x16) ----
#define WARP_IDX                                   \
    int tid = threadIdx.x;                         \
    int lane = tid & 31, wid = tid >> 5;           \
    int wr = (wid >> 2) * 32, wc = (wid & 3) * 16; \
    int g = lane >> 2, tig = lane & 3;

#define ACC_ROW(mi,e) (wr + (mi)*16 + g + ((e)>>1)*8)
#define ACC_COL(ni,e) (wc + (ni)*8 + tig*2 + ((e)&1))

__device__ __forceinline__ void mma_tile8(const float (*As)[PA_], const float (*Bs)[PB_],
                                          float (&acc)[2][2][4],
                                          int wr, int wc, int g, int tig)
{
#pragma unroll
    for (int kb = 0; kb < 64; kb += 8) {
        uint32_t a[2][4], b[2][2];
#pragma unroll
        for (int mi = 0; mi < 2; mi++) {
            int r0 = wr + mi*16 + g;
            a[mi][0] = __float_as_uint(As[r0    ][kb + tig    ]);
            a[mi][1] = __float_as_uint(As[r0 + 8][kb + tig    ]);
            a[mi][2] = __float_as_uint(As[r0    ][kb + tig + 4]);
            a[mi][3] = __float_as_uint(As[r0 + 8][kb + tig + 4]);
        }
#pragma unroll
        for (int ni = 0; ni < 2; ni++) {
            int c0 = wc + ni*8 + g;
            b[ni][0] = __float_as_uint(Bs[kb + tig    ][c0]);
            b[ni][1] = __float_as_uint(Bs[kb + tig + 4][c0]);
        }
#pragma unroll
        for (int mi = 0; mi < 2; mi++)
#pragma unroll
            for (int ni = 0; ni < 2; ni++)
                mma8(acc[mi][ni], a[mi], b[ni]);
    }
}

__device__ __forceinline__ void mma_tile2r(const float (*As)[PA_],
        const float (*B1)[PA_], const float (*B2)[PA_],
        float (&c1)[2][2][4], float (&c2)[2][2][4],
        int wr, int wc, int g, int tig)
{
#pragma unroll
    for (int kb = 0; kb < 64; kb += 8) {
        uint32_t a[2][4], b1[2][2], b2[2][2];
#pragma unroll
        for (int mi = 0; mi < 2; mi++) {
            int r0 = wr + mi*16 + g;
            a[mi][0] = __float_as_uint(As[r0    ][kb + tig    ]);
            a[mi][1] = __float_as_uint(As[r0 + 8][kb + tig    ]);
            a[mi][2] = __float_as_uint(As[r0    ][kb + tig + 4]);
            a[mi][3] = __float_as_uint(As[r0 + 8][kb + tig + 4]);
        }
#pragma unroll
        for (int ni = 0; ni < 2; ni++) {
            int c0 = wc + ni*8 + g;
            b1[ni][0] = __float_as_uint(B1[c0][kb + tig    ]);
            b1[ni][1] = __float_as_uint(B1[c0][kb + tig + 4]);
            b2[ni][0] = __float_as_uint(B2[c0][kb + tig    ]);
            b2[ni][1] = __float_as_uint(B2[c0][kb + tig + 4]);
        }
#pragma unroll
        for (int mi = 0; mi < 2; mi++)
#pragma unroll
        for (int ni = 0; ni < 2; ni++) {
            mma8(c1[mi][ni], a[mi], b1[ni]);
            mma8(c2[mi][ni], a[mi], b2[ni]);
        }
    }
}

// ---- 16-warp layout (512 threads, warp tile 16x16) ----
#define WARP_IDX16                                 \
    int tid = threadIdx.x;                         \
    int lane = tid & 31, wid = tid >> 5;           \
    int wr = (wid >> 2) * 16, wc = (wid & 3) * 16; \
    int g = lane >> 2, tig = lane & 3;

__device__ __forceinline__ void mma_tile16(const float (*As)[PA_], const float (*Bs)[PB_],
                                           float (&acc)[2][4],
                                           int wr, int wc, int g, int tig)
{
#pragma unroll
    for (int kb = 0; kb < 64; kb += 8) {
        uint32_t a[4], b[2][2];
        a[0] = __float_as_uint(As[wr + g    ][kb + tig    ]);
        a[1] = __float_as_uint(As[wr + g + 8][kb + tig    ]);
        a[2] = __float_as_uint(As[wr + g    ][kb + tig + 4]);
        a[3] = __float_as_uint(As[wr + g + 8][kb + tig + 4]);
#pragma unroll
        for (int ni = 0; ni < 2; ni++) {
            int c0 = wc + ni*8 + g;
            b[ni][0] = __float_as_uint(Bs[kb + tig    ][c0]);
            b[ni][1] = __float_as_uint(Bs[kb + tig + 4][c0]);
        }
        mma8(acc[0], a, b[0]);
        mma8(acc[1], a, b[1]);
    }
}

__device__ __forceinline__ void mma_tile16r(const float (*As)[PA_], const float (*Bs)[PA_],
                                            float (&acc)[2][4],
                                            int wr, int wc, int g, int tig)
{
#pragma unroll
    for (int kb = 0; kb < 64; kb += 8) {
        uint32_t a[4], b[2][2];
        a[0] = __float_as_uint(As[wr + g    ][kb + tig    ]);
        a[1] = __float_as_uint(As[wr + g + 8][kb + tig    ]);
        a[2] = __float_as_uint(As[wr + g    ][kb + tig + 4]);
        a[3] = __float_as_uint(As[wr + g + 8][kb + tig + 4]);
#pragma unroll
        for (int ni = 0; ni < 2; ni++) {
            int c0 = wc + ni*8 + g;
            b[ni][0] = __float_as_uint(Bs[c0][kb + tig    ]);
            b[ni][1] = __float_as_uint(Bs[c0][kb + tig + 4]);
        }
        mma8(acc[0], a, b[0]);
        mma8(acc[1], a, b[1]);
    }
}

// ---------------- staging helpers ----------------------------------------------
__device__ __forceinline__ void ldg4_256(const float* __restrict__ p, int ld, float4 (&v)[4]) {
    int t = threadIdx.x * 4;
#pragma unroll
    for (int u = 0; u < 4; u++) {
        int l = t + u*1024;
        v[u] = *(const float4*)(p + (size_t)(l >> 6)*ld + (l & 63));
    }
}
template<int P>
__device__ __forceinline__ void sts4_256(float (*Ts)[P], const float4 (&v)[4]) {
    int t = threadIdx.x * 4;
#pragma unroll
    for (int u = 0; u < 4; u++) {
        int l = t + u*1024;
        *(float4*)&Ts[l >> 6][l & 63] = tf4(v[u]);
    }
}
template<int P>
__device__ __forceinline__ void stage512f(float (*Ts)[P], const float* __restrict__ p, int ld) {
    int t = threadIdx.x * 4;
#pragma unroll
    for (int u = 0; u < 2; u++) {
        int l = t + u*2048, r = l >> 6, c = l & 63;
        float4 v = *(const float4*)(p + (size_t)r*ld + c);
        *(float4*)&Ts[r][c] = tf4(v);
    }
}
// 512-thread register load (2 float4 per thread) / smem store
__device__ __forceinline__ void ld512r(const float* __restrict__ p, int ld, float4 (&v)[2]) {
    int t = threadIdx.x * 4;
#pragma unroll
    for (int u = 0; u < 2; u++) {
        int l = t + u*2048;
        v[u] = *(const float4*)(p + (size_t)(l >> 6)*ld + (l & 63));
    }
}
template<int P>
__device__ __forceinline__ void st512r(float (*Ts)[P], const float4 (&v)[2]) {
    int t = threadIdx.x * 4;
#pragma unroll
    for (int u = 0; u < 2; u++) {
        int l = t + u*2048;
        *(float4*)&Ts[l >> 6][l & 63] = tf4(v[u]);
    }
}

// ---------------- fused projection ----------------------------------------------
__global__ __launch_bounds__(256, 2) void proj_kernel(
    const float* __restrict__ x,  const float* __restrict__ Wq,
    const float* __restrict__ Wk, const float* __restrict__ Wv,
    const float* __restrict__ Ww1,const float* __restrict__ Wb)
{
    extern __shared__ float sm[];
    float (*Ab0)[PA_] = (float(*)[PA_])sm;
    float (*Ab1)[PA_] = (float(*)[PA_])(sm + ASZ);
    float (*Bb0)[PB_] = (float(*)[PB_])(sm + 2*ASZ);
    float (*Bb1)[PB_] = (float(*)[PB_])(sm + 2*ASZ + BSZ);
    float (*Ab[2])[PA_] = {Ab0, Ab1};
    float (*Bb[2])[PB_] = {Bb0, Bb1};
    WARP_IDX;
    int bm = blockIdx.y * 64, bn = blockIdx.x * 64;
    float acc[2][2][4] = {};
    float4 va[4], vb[4];

    auto ldB = [&](int kt) {
        int t = tid * 4;
#pragma unroll
        for (int u = 0; u < 4; u++) {
            int l = t + u*1024, r = l >> 6, c = l & 63;
            int kk = kt + r;
            if (bn < 3072) {
                const float* W = (bn < 1024) ? Wq : (bn < 2048) ? Wk : Wv;
                vb[u] = *(const float4*)&W[(size_t)kk*DMM + ((bn + c) & 1023)];
            } else {
                float tv[4];
#pragma unroll
                for (int q2 = 0; q2 < 4; q2++) {
                    int nn = bn + c + q2;
                    tv[q2] = (nn < 3104) ? Ww1[kk*RNK + (nn - 3072)]
                           : (nn < NPROJ) ? Wb[kk*HH + (nn - 3104)] : 0.f;
                }
                vb[u] = make_float4(tv[0], tv[1], tv[2], tv[3]);
            }
        }
    };

    ldg4_256(&x[(size_t)bm*DMM], DMM, va);
    ldB(0);
    sts4_256<PA_>(Ab[0], va);
    sts4_256<PB_>(Bb[0], vb);
    __syncthreads();
    int cur = 0;
    for (int i = 0; i < 16; i++) {
        if (i < 15) { ldg4_256(&x[(size_t)bm*DMM + (i+1)*64], DMM, va); ldB((i+1)*64); }
        mma_tile8(Ab[cur], Bb[cur], acc, wr, wc, g, tig);
        if (i < 15) {
            sts4_256<PA_>(Ab[cur^1], va);
            sts4_256<PB_>(Bb[cur^1], vb);
            __syncthreads();
            cur ^= 1;
        }
    }
#pragma unroll
    for (int mi = 0; mi < 2; mi++)
#pragma unroll
    for (int ni = 0; ni < 2; ni++)
#pragma unroll
    for (int e = 0; e < 4; e++) {
        int row = bm + ACC_ROW(mi, e);
        int col = bn + ACC_COL(ni, e);
        float v = acc[mi][ni][e];
        if      (col < 1024)  g_q[(size_t)row*DMM + col] = v;
        else if (col < 2048)  g_k[(size_t)row*DMM + (col - 1024)] = v;
        else if (col < 3072)  g_v[(size_t)row*DMM + (col - 2048)] = v;
        else if (col < 3104)  g_xw1[row*RNK + (col - 3072)] = v;
        else if (col < NPROJ) g_beta[row*HH + (col - 3104)] = 2.f/(1.f + expf(-v));
    }
}

// ---------------- generic C = A@B -------------------------------------------------
__global__ __launch_bounds__(256, 2) void gemm_tc(
    const float* __restrict__ A, const float* __restrict__ B,
    float* __restrict__ C, int N, int K)
{
    extern __shared__ float sm[];
    float (*Ab0)[PA_] = (float(*)[PA_])sm;
    float (*Ab1)[PA_] = (float(*)[PA_])(sm + ASZ);
    float (*Bb0)[PB_] = (float(*)[PB_])(sm + 2*ASZ);
    float (*Bb1)[PB_] = (float(*)[PB_])(sm + 2*ASZ + BSZ);
    float (*Ab[2])[PA_] = {Ab0, Ab1};
    float (*Bb[2])[PB_] = {Bb0, Bb1};
    WARP_IDX;
    int bm = blockIdx.y * 64, bn = blockIdx.x * 64;
    float acc[2][2][4] = {};
    float4 va[4], vb[4];

    auto ldA = [&](int kt) {
        int t = tid * 4;
#pragma unroll
        for (int u = 0; u < 4; u++) {
            int l = t + u*1024, r = l >> 6, c = l & 63;
            va[u] = (kt + c < K) ? *(const float4*)&A[(size_t)(bm + r)*K + kt + c]
                                 : make_float4(0.f, 0.f, 0.f, 0.f);
        }
    };
    auto ldB = [&](int kt) {
        int t = tid * 4;
#pragma unroll
        for (int u = 0; u < 4; u++) {
            int l = t + u*1024, r = l >> 6, c = l & 63;
            vb[u] = (kt + r < K) ? *(const float4*)&B[(size_t)(kt + r)*N + bn + c]
                                 : make_float4(0.f, 0.f, 0.f, 0.f);
        }
    };

    int nk = (K + 63) / 64;
    ldA(0); ldB(0);
    sts4_256<PA_>(Ab[0], va);
    sts4_256<PB_>(Bb[0], vb);
    __syncthreads();
    int cur = 0;
    for (int i = 0; i < nk; i++) {
        if (i < nk - 1) { ldA((i+1)*64); ldB((i+1)*64); }
        mma_tile8(Ab[cur], Bb[cur], acc, wr, wc, g, tig);
        if (i < nk - 1) {
            sts4_256<PA_>(Ab[cur^1], va);
            sts4_256<PB_>(Bb[cur^1], vb);
            __syncthreads();
            cur ^= 1;
        }
    }
#pragma unroll
    for (int mi = 0; mi < 2; mi++)
#pragma unroll
    for (int ni = 0; ni < 2; ni++)
#pragma unroll
    for (int e = 0; e < 4; e++)
        C[(size_t)(bm + ACC_ROW(mi, e))*N + bn + ACC_COL(ni, e)] = acc[mi][ni][e];
}

// ---------------- conv + SiLU + per-head L2 norm ----------------------------------
__global__ void conv_norm_kernel(const float* __restrict__ conv_w)
{
    int t = blockIdx.x;
    int c = threadIdx.x;
    float x0  = g_wpre[t*DMM + c];
    float xm1 = (t >= 1) ? g_wpre[(t-1)*DMM + c] : 0.f;
    float xm2 = (t >= 2) ? g_wpre[(t-2)*DMM + c] : 0.f;
    float y = conv_w[c*3+0]*xm2 + conv_w[c*3+1]*xm1 + conv_w[c*3+2]*x0;
    y = y / (1.f + expf(-y));
    float y2 = y * y;
#pragma unroll
    for (int o = 16; o; o >>= 1) y2 += __shfl_xor_sync(0xffffffffu, y2, o);
    __shared__ float wsum[32];
    if ((c & 31) == 0) wsum[c >> 5] = y2;
    __syncthreads();
    int h = c >> 6;
    float ss = wsum[2*h] + wsum[2*h+1];
    g_w[t*DMM + c] = y * rsqrtf(ss + 1e-6f);
}

// ---------------- merged: diag Md/MkD + unit-lower inversion -----------------------
__global__ __launch_bounds__(256) void diaginv_kernel()
{
    __shared__ float Aw[64][PA_];
    __shared__ float Bk[64][PA_];
    __shared__ float L[64][65];
    __shared__ float X[64][65];
    int J = blockIdx.x, h = blockIdx.y;
    WARP_IDX;
    {
        int t = tid * 4;
#pragma unroll
        for (int u = 0; u < 4; u++) {
            int l = t + u*1024, r = l >> 6, c = l & 63;
            *(float4*)&Aw[r][c] = tf4(*(const float4*)&g_w[(size_t)(J*64 + r)*DMM + h*64 + c]);
            *(float4*)&Bk[r][c] = tf4(*(const float4*)&g_k[(size_t)(J*64 + r)*DMM + h*64 + c]);
        }
    }
    __syncthreads();
    float am[2][2][4] = {}, amk[2][2][4] = {};
    mma_tile2r(Aw, Aw, Bk, am, amk, wr, wc, g, tig);
    size_t ofs = ((size_t)h*NT + J)*4096;
#pragma unroll
    for (int mi = 0; mi < 2; mi++)
#pragma unroll
    for (int ni = 0; ni < 2; ni++)
#pragma unroll
    for (int e = 0; e < 4; e += 2) {
        int r = ACC_ROW(mi, e), c = ACC_COL(ni, e);
        float be = g_beta[(size_t)(J*64 + r)*HH + h];
        L[r][c]   = (r > c    ) ? be*am[mi][ni][e]   : (r == c     ? 1.f : 0.f);
        L[r][c+1] = (r > c + 1) ? be*am[mi][ni][e+1] : (r == c + 1 ? 1.f : 0.f);
        X[r][c]   = (r == c    ) ? 1.f : 0.f;
        X[r][c+1] = (r == c + 1) ? 1.f : 0.f;
        float2 mk;
        mk.x = (r > c    ) ? -be*amk[mi][ni][e]   : 0.f;
        mk.y = (r > c + 1) ? -be*amk[mi][ni][e+1] : 0.f;
        *(float2*)&g_MkD[ofs + r*64 + c] = mk;
    }
    __syncthreads();
    // invert: each thread owns one column; all deps intra-thread (no syncs needed)
    if (tid < 64) {
        int c = tid;
        for (int r = c + 1; r < 64; r++) {
            float a = 0.f;
            for (int s = c; s < r; s++) a += L[r][s] * X[s][c];
            X[r][c] = -a;
        }
    }
    __syncthreads();
    for (int l = tid; l < 4096; l += 256)
        g_invA[ofs + l] = X[l >> 6][l & 63];
}

// ---------------- fused row scan: Aqw/QK + solve + online softmax + PV -------------
__global__ __launch_bounds__(512) void row_kernel()
{
    extern __shared__ float sm[];
    float (*Qsm)[PA_]  = (float(*)[PA_])(sm);
    float (*Psm)[PA_]  = (float(*)[PA_])(sm + ASZ);       // Pneg = -P state
    float (*Gtmp)[PA_] = (float(*)[PA_])(sm + 2*ASZ);
    float (*Wrow)[PA_] = (float(*)[PA_])(sm + 3*ASZ);     // w_J, later exp tile
    float (*Krow)[PA_] = (float(*)[PA_])(sm + 4*ASZ);     // k_J
    float (*Binv)[PB_] = (float(*)[PB_])(sm + 5*ASZ);
    float (*MkDs)[PB_] = (float(*)[PB_])(sm + 5*ASZ + BSZ);
    float (*BWn)[PB_]  = (float(*)[PB_])(sm + 5*ASZ + 2*BSZ);  // -beta*w_J
    float (*Vsm)[PB_]  = (float(*)[PB_])(sm + 5*ASZ + 3*BSZ);  // v_J
    __shared__ float red[64][8];
    int h = blockIdx.x;
    int I = NT - 1 - blockIdx.y;    // heavy rows launch first
    WARP_IDX16;
    int wcg = wid & 3;
    int r0 = wr + g, r1 = wr + g + 8;
    size_t hofs = (size_t)h*NT*4096;

    // stage Q_I once
    stage512f<PA_>(Qsm, &g_q[(size_t)(I*64)*DMM + h*64], DMM);

    // prefetch registers for J = I
    float4 vw[2], vk[2], vv[2], vbi[2], vmk[2];
    float vbe[2];
    {
        int t = tid * 4;
#pragma unroll
        for (int u = 0; u < 2; u++) {
            int l = t + u*2048, r = l >> 6, c = l & 63;
            vw[u] = *(const float4*)&g_w[(size_t)(I*64 + r)*DMM + h*64 + c];
            vk[u] = *(const float4*)&g_k[(size_t)(I*64 + r)*DMM + h*64 + c];
            vv[u] = *(const float4*)&g_v[(size_t)(I*64 + r)*DMM + h*64 + c];
            vbe[u] = g_beta[(size_t)(I*64 + r)*HH + h];
            vbi[u] = *(const float4*)&g_invA[hofs + (size_t)I*4096 + l];
            vmk[u] = *(const float4*)&g_MkD [hofs + (size_t)I*4096 + l];
        }
    }

    float Pn[2][4] = {};            // Pneg state
    float O[2][4]  = {};            // unnormalized output
    float m0 = -1e30f, m1 = -1e30f;
    float s0 = 0.f,    s1 = 0.f;

    for (int J = I; J >= 0; J--) {
        // ---- store staged operands from prefetch registers ----
        {
            int t = tid * 4;
#pragma unroll
            for (int u = 0; u < 2; u++) {
                int l = t + u*2048, r = l >> 6, c = l & 63;
                *(float4*)&Wrow[r][c] = tf4(vw[u]);
                float nb = -vbe[u];
                float4 w4 = make_float4(vw[u].x*nb, vw[u].y*nb, vw[u].z*nb, vw[u].w*nb);
                *(float4*)&BWn[r][c] = tf4(w4);
                *(float4*)&Krow[r][c] = tf4(vk[u]);
                *(float4*)&Vsm [r][c] = tf4(vv[u]);
            }
        }
        if (J < I) {
#pragma unroll
            for (int ni = 0; ni < 2; ni++) {
                int c0 = wc + ni*8 + tig*2;
                Psm[r0][c0]   = to_tf32(Pn[ni][0]);
                Psm[r0][c0+1] = to_tf32(Pn[ni][1]);
                Psm[r1][c0]   = to_tf32(Pn[ni][2]);
                Psm[r1][c0+1] = to_tf32(Pn[ni][3]);
            }
        }
        __syncthreads();

        // acc = Q@W^T (+ Pneg@W^T), sacc = Q@K^T (+ Pneg@K^T)
        float acc[2][4] = {}, sacc[2][4] = {};
        mma_tile16r(Qsm, Wrow, acc,  wr, wc, g, tig);
        mma_tile16r(Qsm, Krow, sacc, wr, wc, g, tig);
        if (J < I) {
            mma_tile16r(Psm, Wrow, acc,  wr, wc, g, tig);
            mma_tile16r(Psm, Krow, sacc, wr, wc, g, tig);
        } else {
#pragma unroll
            for (int ni = 0; ni < 2; ni++) {
                int c0 = wc + ni*8 + tig*2;
                if (c0     > r0) acc[ni][0] = 0.f;
                if (c0 + 1 > r0) acc[ni][1] = 0.f;
                if (c0     > r1) acc[ni][2] = 0.f;
                if (c0 + 1 > r1) acc[ni][3] = 0.f;
            }
        }
        // store Binv/MkD (prefetched) + Gtmp
        st512r<PB_>(Binv, vbi);
        st512r<PB_>(MkDs, vmk);
#pragma unroll
        for (int ni = 0; ni < 2; ni++) {
            int c0 = wc + ni*8 + tig*2;
            Gtmp[r0][c0]   = to_tf32(acc[ni][0]);
            Gtmp[r0][c0+1] = to_tf32(acc[ni][1]);
            Gtmp[r1][c0]   = to_tf32(acc[ni][2]);
            Gtmp[r1][c0+1] = to_tf32(acc[ni][3]);
        }
        __syncthreads();

        // prefetch next J's operands (latency hidden behind remaining MMAs)
        if (J > 0) {
            int Jn = J - 1;
            int t = tid * 4;
#pragma unroll
            for (int u = 0; u < 2; u++) {
                int l = t + u*2048, r = l >> 6, c = l & 63;
                vw[u] = *(const float4*)&g_w[(size_t)(Jn*64 + r)*DMM + h*64 + c];
                vk[u] = *(const float4*)&g_k[(size_t)(Jn*64 + r)*DMM + h*64 + c];
                vv[u] = *(const float4*)&g_v[(size_t)(Jn*64 + r)*DMM + h*64 + c];
                vbe[u] = g_beta[(size_t)(Jn*64 + r)*HH + h];
                vbi[u] = *(const float4*)&g_invA[hofs + (size_t)Jn*4096 + l];
                vmk[u] = *(const float4*)&g_MkD [hofs + (size_t)Jn*4096 + l];
            }
        }

        float Gf[2][4] = {};
        mma_tile16(Gtmp, Binv, Gf, wr, wc, g, tig);
        __syncthreads();
#pragma unroll
        for (int ni = 0; ni < 2; ni++) {
            int c0 = wc + ni*8 + tig*2;
            Gtmp[r0][c0]   = to_tf32(Gf[ni][0]);
            Gtmp[r0][c0+1] = to_tf32(Gf[ni][1]);
            Gtmp[r1][c0]   = to_tf32(Gf[ni][2]);
            Gtmp[r1][c0+1] = to_tf32(Gf[ni][3]);
        }
        __syncthreads();
        mma_tile16(Gtmp, MkDs, sacc, wr, wc, g, tig);   // sacc -= G@MkD (preneg)
        mma_tile16(Gtmp, BWn,  Pn,   wr, wc, g, tig);   // Pneg -= G@BW

        // ---- online softmax ----
        float tv[2][4];
        float lm0 = -1e30f, lm1 = -1e30f;
#pragma unroll
        for (int ni = 0; ni < 2; ni++) {
            int c0 = wc + ni*8 + tig*2;
#pragma unroll
            for (int e = 0; e < 4; e++) {
                float v = sacc[ni][e] * SCALE;
                int rr = (e < 2) ? r0 : r1;
                int cc = c0 + (e & 1);
                if (J == I && cc > rr) v = -1e30f;
                tv[ni][e] = v;
                if (e < 2) lm0 = fmaxf(lm0, v); else lm1 = fmaxf(lm1, v);
            }
        }
#pragma unroll
        for (int o = 1; o < 4; o <<= 1) {
            lm0 = fmaxf(lm0, __shfl_xor_sync(0xffffffffu, lm0, o));
            lm1 = fmaxf(lm1, __shfl_xor_sync(0xffffffffu, lm1, o));
        }
        if (tig == 0) { red[r0][wcg] = lm0; red[r1][wcg] = lm1; }
        __syncthreads();
        float m0n = fmaxf(m0, fmaxf(fmaxf(red[r0][0], red[r0][1]),
                                    fmaxf(red[r0][2], red[r0][3])));
        float m1n = fmaxf(m1, fmaxf(fmaxf(red[r1][0], red[r1][1]),
                                    fmaxf(red[r1][2], red[r1][3])));
        float sc0 = __expf(m0 - m0n), sc1 = __expf(m1 - m1n);
        m0 = m0n; m1 = m1n;
        s0 *= sc0; s1 *= sc1;
#pragma unroll
        for (int ni = 0; ni < 2; ni++)
#pragma unroll
        for (int e = 0; e < 4; e++)
            O[ni][e] *= (e < 2) ? sc0 : sc1;

        float ls0 = 0.f, ls1 = 0.f;
#pragma unroll
        for (int ni = 0; ni < 2; ni++) {
            int c0 = wc + ni*8 + tig*2;
#pragma unroll
            for (int e = 0; e < 4; e++) {
                float p = __expf(tv[ni][e] - ((e < 2) ? m0 : m1));
                if (e < 2) ls0 += p; else ls1 += p;
                int rr = (e < 2) ? r0 : r1;
                Wrow[rr][c0 + (e & 1)] = to_tf32(p);
            }
        }
#pragma unroll
        for (int o = 1; o < 4; o <<= 1) {
            ls0 += __shfl_xor_sync(0xffffffffu, ls0, o);
            ls1 += __shfl_xor_sync(0xffffffffu, ls1, o);
        }
        if (tig == 0) { red[r0][4 + wcg] = ls0; red[r1][4 + wcg] = ls1; }
        __syncthreads();
        s0 += red[r0][4] + red[r0][5] + red[r0][6] + red[r0][7];
        s1 += red[r1][4] + red[r1][5] + red[r1][6] + red[r1][7];

        mma_tile16(Wrow, Vsm, O, wr, wc, g, tig);       // O += exp(P) @ V_J
        __syncthreads();
    }

    float i0 = 1.f / s0, i1 = 1.f / s1;
#pragma unroll
    for (int ni = 0; ni < 2; ni++) {
        int c0 = wc + ni*8 + tig*2;
        float2 v0 = make_float2(O[ni][0]*i0, O[ni][1]*i0);
        float2 v1 = make_float2(O[ni][2]*i1, O[ni][3]*i1);
        *(float2*)&g_o[(size_t)(I*64 + r0)*DMM + h*64 + c0] = v0;
        *(float2*)&g_o[(size_t)(I*64 + r1)*DMM + h*64 + c0] = v1;
    }
}

// ---------------- launcher ----------------------------------------------------------
extern "C" void kernel_launch(void* const* d_in, const int* in_sizes, int n_in,
                              void* d_out, int out_size)
{
    const float* x     = (const float*)d_in[0];
    const float* Wq    = (const float*)d_in[1];
    const float* Wk    = (const float*)d_in[2];
    const float* Wv    = (const float*)d_in[3];
    const float* Ww1   = (const float*)d_in[4];
    const float* Ww2   = (const float*)d_in[5];
    const float* convw = (const float*)d_in[6];
    const float* Wb    = (const float*)d_in[7];
    const float* Wo    = (const float*)d_in[8];

    float *xw1, *wpre, *o;
    cudaGetSymbolAddress((void**)&xw1,  g_xw1);
    cudaGetSymbolAddress((void**)&wpre, g_wpre);
    cudaGetSymbolAddress((void**)&o,    g_o);

    const int SM_DB  = (2*ASZ + 2*BSZ) * 4;     // 71680 B
    const int SM_ROW = (5*ASZ + 4*BSZ) * 4;     // 160768 B
    static bool attr_set = false;
    if (!attr_set) {
        cudaFuncSetAttribute(proj_kernel, cudaFuncAttributeMaxDynamicSharedMemorySize, SM_DB);
        cudaFuncSetAttribute(gemm_tc,     cudaFuncAttributeMaxDynamicSharedMemorySize, SM_DB);
        cudaFuncSetAttribute(row_kernel,  cudaFuncAttributeMaxDynamicSharedMemorySize, SM_ROW);
        attr_set = true;
    }

    dim3 blk(256);

    proj_kernel<<<dim3((NPROJ + 63)/64, 16), blk, SM_DB>>>(x, Wq, Wk, Wv, Ww1, Wb);
    gemm_tc<<<dim3(16, 16), blk, SM_DB>>>(xw1, Ww2, wpre, DMM, RNK);
    conv_norm_kernel<<<TT, 1024>>>(convw);
    diaginv_kernel<<<dim3(NT, HH), blk>>>();
    row_kernel<<<dim3(HH, NT), 512, SM_ROW>>>();
    gemm_tc<<<dim3(16, 16), blk, SM_DB>>>(o, Wo, (float*)d_out, DMM, DMM);
}

// round 14
// speedup vs baseline: 1.0115x; 1.0115x over previous
#include <cuda_runtime.h>
#include <math.h>
#include <stdint.h>

#define TT   1024
#define DMM  1024
#define HH   16
#define RNK  32
#define NT   16
#define SCALE 0.125f
#define NPROJ 3120     // 3*1024 + 32 + 16

#define PA_  68
#define PB_  72
#define ASZ  (64*PA_)
#define BSZ  (64*PB_)

// ---------------- scratch (device globals) ----------------------------------
__device__ float g_q   [TT*DMM];
__device__ float g_k   [TT*DMM];
__device__ float g_v   [TT*DMM];
__device__ float g_wpre[TT*DMM];
__device__ float g_w   [TT*DMM];
__device__ float g_xw1 [TT*RNK];
__device__ float g_beta[TT*HH];
__device__ float g_invA[HH*NT*64*64];
__device__ float g_MkD [HH*NT*64*64]; // strict diag Mk blocks, NEGATED
__device__ float g_o [TT*DMM];

// ---------------- tf32 helpers ------------------------------------------------
__device__ __forceinline__ float to_tf32(float x) {
    uint32_t u; asm("cvt.rna.tf32.f32 %0, %1;" : "=r"(u) : "f"(x));
    return __uint_as_float(u);
}
__device__ __forceinline__ float4 tf4(float4 v) {
    v.x = to_tf32(v.x); v.y = to_tf32(v.y); v.z = to_tf32(v.z); v.w = to_tf32(v.w);
    return v;
}

__device__ __forceinline__ void mma8(float (&c)[4], const uint32_t (&a)[4],
                                     const uint32_t (&b)[2]) {
    asm volatile(
        "mma.sync.aligned.m16n8k8.row.col.f32.tf32.tf32.f32 "
        "{%0,%1,%2,%3},{%4,%5,%6,%7},{%8,%9},{%0,%1,%2,%3};"
        : "+f"(c[0]), "+f"(c[1]), "+f"(c[2]), "+f"(c[3])
        : "r"(a[0]), "r"(a[1]), "r"(a[2]), "r"(a[3]), "r"(b[0]), "r"(b[1]));
}

// ---- 8-warp layout (256 threads, warp tile 32x16) ----
#define WARP_IDX                                   \
    int tid = threadIdx.x;                         \
    int lane = tid & 31, wid = tid >> 5;           \
    int wr = (wid >> 2) * 32, wc = (wid & 3) * 16; \
    int g = lane >> 2, tig = lane & 3;

#define ACC_ROW(mi,e) (wr + (mi)*16 + g + ((e)>>1)*8)
#define ACC_COL(ni,e) (wc + (ni)*8 + tig*2 + ((e)&1))

__device__ __forceinline__ void mma_tile8(const float (*As)[PA_], const float (*Bs)[PB_],
                                          float (&acc)[2][2][4],
                                          int wr, int wc, int g, int tig)
{
#pragma unroll
    for (int kb = 0; kb < 64; kb += 8) {
        uint32_t a[2][4], b[2][2];
#pragma unroll
        for (int mi = 0; mi < 2; mi++) {
            int r0 = wr + mi*16 + g;
            a[mi][0] = __float_as_uint(As[r0    ][kb + tig    ]);
            a[mi][1] = __float_as_uint(As[r0 + 8][kb + tig    ]);
            a[mi][2] = __float_as_uint(As[r0    ][kb + tig + 4]);
            a[mi][3] = __float_as_uint(As[r0 + 8][kb + tig + 4]);
        }
#pragma unroll
        for (int ni = 0; ni < 2; ni++) {
            int c0 = wc + ni*8 + g;
            b[ni][0] = __float_as_uint(Bs[kb + tig    ][c0]);
            b[ni][1] = __float_as_uint(Bs[kb + tig + 4][c0]);
        }
#pragma unroll
        for (int mi = 0; mi < 2; mi++)
#pragma unroll
            for (int ni = 0; ni < 2; ni++)
                mma8(acc[mi][ni], a[mi], b[ni]);
    }
}

__device__ __forceinline__ void mma_tile2r(const float (*As)[PA_],
        const float (*B1)[PA_], const float (*B2)[PA_],
        float (&c1)[2][2][4], float (&c2)[2][2][4],
        int wr, int wc, int g, int tig)
{
#pragma unroll
    for (int kb = 0; kb < 64; kb += 8) {
        uint32_t a[2][4], b1[2][2], b2[2][2];
#pragma unroll
        for (int mi = 0; mi < 2; mi++) {
            int r0 = wr + mi*16 + g;
            a[mi][0] = __float_as_uint(As[r0    ][kb + tig    ]);
            a[mi][1] = __float_as_uint(As[r0 + 8][kb + tig    ]);
            a[mi][2] = __float_as_uint(As[r0    ][kb + tig + 4]);
            a[mi][3] = __float_as_uint(As[r0 + 8][kb + tig + 4]);
        }
#pragma unroll
        for (int ni = 0; ni < 2; ni++) {
            int c0 = wc + ni*8 + g;
            b1[ni][0] = __float_as_uint(B1[c0][kb + tig    ]);
            b1[ni][1] = __float_as_uint(B1[c0][kb + tig + 4]);
            b2[ni][0] = __float_as_uint(B2[c0][kb + tig    ]);
            b2[ni][1] = __float_as_uint(B2[c0][kb + tig + 4]);
        }
#pragma unroll
        for (int mi = 0; mi < 2; mi++)
#pragma unroll
        for (int ni = 0; ni < 2; ni++) {
            mma8(c1[mi][ni], a[mi], b1[ni]);
            mma8(c2[mi][ni], a[mi], b2[ni]);
        }
    }
}

// ---- 16-warp layout (512 threads, warp tile 16x16) ----
#define WARP_IDX16                                 \
    int tid = threadIdx.x;                         \
    int lane = tid & 31, wid = tid >> 5;           \
    int wr = (wid >> 2) * 16, wc = (wid & 3) * 16; \
    int g = lane >> 2, tig = lane & 3;

__device__ __forceinline__ void mma_tile16(const float (*As)[PA_], const float (*Bs)[PB_],
                                           float (&acc)[2][4],
                                           int wr, int wc, int g, int tig)
{
#pragma unroll
    for (int kb = 0; kb < 64; kb += 8) {
        uint32_t a[4], b[2][2];
        a[0] = __float_as_uint(As[wr + g    ][kb + tig    ]);
        a[1] = __float_as_uint(As[wr + g + 8][kb + tig    ]);
        a[2] = __float_as_uint(As[wr + g    ][kb + tig + 4]);
        a[3] = __float_as_uint(As[wr + g + 8][kb + tig + 4]);
#pragma unroll
        for (int ni = 0; ni < 2; ni++) {
            int c0 = wc + ni*8 + g;
            b[ni][0] = __float_as_uint(Bs[kb + tig    ][c0]);
            b[ni][1] = __float_as_uint(Bs[kb + tig + 4][c0]);
        }
        mma8(acc[0], a, b[0]);
        mma8(acc[1], a, b[1]);
    }
}

__device__ __forceinline__ void mma_tile16r(const float (*As)[PA_], const float (*Bs)[PA_],
                                            float (&acc)[2][4],
                                            int wr, int wc, int g, int tig)
{
#pragma unroll
    for (int kb = 0; kb < 64; kb += 8) {
        uint32_t a[4], b[2][2];
        a[0] = __float_as_uint(As[wr + g    ][kb + tig    ]);
        a[1] = __float_as_uint(As[wr + g + 8][kb + tig    ]);
        a[2] = __float_as_uint(As[wr + g    ][kb + tig + 4]);
        a[3] = __float_as_uint(As[wr + g + 8][kb + tig + 4]);
#pragma unroll
        for (int ni = 0; ni < 2; ni++) {
            int c0 = wc + ni*8 + g;
            b[ni][0] = __float_as_uint(Bs[c0][kb + tig    ]);
            b[ni][1] = __float_as_uint(Bs[c0][kb + tig + 4]);
        }
        mma8(acc[0], a, b[0]);
        mma8(acc[1], a, b[1]);
    }
}

// ---------------- staging helpers ----------------------------------------------
__device__ __forceinline__ void ldg4_256(const float* __restrict__ p, int ld, float4 (&v)[4]) {
    int t = threadIdx.x * 4;
#pragma unroll
    for (int u = 0; u < 4; u++) {
        int l = t + u*1024;
        v[u] = *(const float4*)(p + (size_t)(l >> 6)*ld + (l & 63));
    }
}
template<int P>
__device__ __forceinline__ void sts4_256(float (*Ts)[P], const float4 (&v)[4]) {
    int t = threadIdx.x * 4;
#pragma unroll
    for (int u = 0; u < 4; u++) {
        int l = t + u*1024;
        *(float4*)&Ts[l >> 6][l & 63] = tf4(v[u]);
    }
}
template<int P>
__device__ __forceinline__ void stage512f(float (*Ts)[P], const float* __restrict__ p, int ld) {
    int t = threadIdx.x * 4;
#pragma unroll
    for (int u = 0; u < 2; u++) {
        int l = t + u*2048, r = l >> 6, c = l & 63;
        float4 v = *(const float4*)(p + (size_t)r*ld + c);
        *(float4*)&Ts[r][c] = tf4(v);
    }
}
template<int P>
__device__ __forceinline__ void st512r(float (*Ts)[P], const float4 (&v)[2]) {
    int t = threadIdx.x * 4;
#pragma unroll
    for (int u = 0; u < 2; u++) {
        int l = t + u*2048;
        *(float4*)&Ts[l >> 6][l & 63] = tf4(v[u]);
    }
}

// ---------------- fused projection ----------------------------------------------
__global__ __launch_bounds__(256, 2) void proj_kernel(
    const float* __restrict__ x,  const float* __restrict__ Wq,
    const float* __restrict__ Wk, const float* __restrict__ Wv,
    const float* __restrict__ Ww1,const float* __restrict__ Wb)
{
    extern __shared__ float sm[];
    float (*Ab0)[PA_] = (float(*)[PA_])sm;
    float (*Ab1)[PA_] = (float(*)[PA_])(sm + ASZ);
    float (*Bb0)[PB_] = (float(*)[PB_])(sm + 2*ASZ);
    float (*Bb1)[PB_] = (float(*)[PB_])(sm + 2*ASZ + BSZ);
    float (*Ab[2])[PA_] = {Ab0, Ab1};
    float (*Bb[2])[PB_] = {Bb0, Bb1};
    WARP_IDX;
    int bm = blockIdx.y * 64, bn = blockIdx.x * 64;
    float acc[2][2][4] = {};
    float4 va[4], vb[4];

    auto ldB = [&](int kt) {
        int t = tid * 4;
#pragma unroll
        for (int u = 0; u < 4; u++) {
            int l = t + u*1024, r = l >> 6, c = l & 63;
            int kk = kt + r;
            if (bn < 3072) {
                const float* W = (bn < 1024) ? Wq : (bn < 2048) ? Wk : Wv;
                vb[u] = *(const float4*)&W[(size_t)kk*DMM + ((bn + c) & 1023)];
            } else {
                float tv[4];
#pragma unroll
                for (int q2 = 0; q2 < 4; q2++) {
                    int nn = bn + c + q2;
                    tv[q2] = (nn < 3104) ? Ww1[kk*RNK + (nn - 3072)]
                           : (nn < NPROJ) ? Wb[kk*HH + (nn - 3104)] : 0.f;
                }
                vb[u] = make_float4(tv[0], tv[1], tv[2], tv[3]);
            }
        }
    };

    ldg4_256(&x[(size_t)bm*DMM], DMM, va);
    ldB(0);
    sts4_256<PA_>(Ab[0], va);
    sts4_256<PB_>(Bb[0], vb);
    __syncthreads();
    int cur = 0;
    for (int i = 0; i < 16; i++) {
        if (i < 15) { ldg4_256(&x[(size_t)bm*DMM + (i+1)*64], DMM, va); ldB((i+1)*64); }
        mma_tile8(Ab[cur], Bb[cur], acc, wr, wc, g, tig);
        if (i < 15) {
            sts4_256<PA_>(Ab[cur^1], va);
            sts4_256<PB_>(Bb[cur^1], vb);
            __syncthreads();
            cur ^= 1;
        }
    }
#pragma unroll
    for (int mi = 0; mi < 2; mi++)
#pragma unroll
    for (int ni = 0; ni < 2; ni++)
#pragma unroll
    for (int e = 0; e < 4; e++) {
        int row = bm + ACC_ROW(mi, e);
        int col = bn + ACC_COL(ni, e);
        float v = acc[mi][ni][e];
        if      (col < 1024)  g_q[(size_t)row*DMM + col] = v;
        else if (col < 2048)  g_k[(size_t)row*DMM + (col - 1024)] = v;
        else if (col < 3072)  g_v[(size_t)row*DMM + (col - 2048)] = v;
        else if (col < 3104)  g_xw1[row*RNK + (col - 3072)] = v;
        else if (col < NPROJ) g_beta[row*HH + (col - 3104)] = 2.f/(1.f + expf(-v));
    }
}

// ---------------- generic C = A@B -------------------------------------------------
__global__ __launch_bounds__(256, 2) void gemm_tc(
    const float* __restrict__ A, const float* __restrict__ B,
    float* __restrict__ C, int N, int K)
{
    extern __shared__ float sm[];
    float (*Ab0)[PA_] = (float(*)[PA_])sm;
    float (*Ab1)[PA_] = (float(*)[PA_])(sm + ASZ);
    float (*Bb0)[PB_] = (float(*)[PB_])(sm + 2*ASZ);
    float (*Bb1)[PB_] = (float(*)[PB_])(sm + 2*ASZ + BSZ);
    float (*Ab[2])[PA_] = {Ab0, Ab1};
    float (*Bb[2])[PB_] = {Bb0, Bb1};
    WARP_IDX;
    int bm = blockIdx.y * 64, bn = blockIdx.x * 64;
    float acc[2][2][4] = {};
    float4 va[4], vb[4];

    auto ldA = [&](int kt) {
        int t = tid * 4;
#pragma unroll
        for (int u = 0; u < 4; u++) {
            int l = t + u*1024, r = l >> 6, c = l & 63;
            va[u] = (kt + c < K) ? *(const float4*)&A[(size_t)(bm + r)*K + kt + c]
                                 : make_float4(0.f, 0.f, 0.f, 0.f);
        }
    };
    auto ldB = [&](int kt) {
        int t = tid * 4;
#pragma unroll
        for (int u = 0; u < 4; u++) {
            int l = t + u*1024, r = l >> 6, c = l & 63;
            vb[u] = (kt + r < K) ? *(const float4*)&B[(size_t)(kt + r)*N + bn + c]
                                 : make_float4(0.f, 0.f, 0.f, 0.f);
        }
    };

    int nk = (K + 63) / 64;
    ldA(0); ldB(0);
    sts4_256<PA_>(Ab[0], va);
    sts4_256<PB_>(Bb[0], vb);
    __syncthreads();
    int cur = 0;
    for (int i = 0; i < nk; i++) {
        if (i < nk - 1) { ldA((i+1)*64); ldB((i+1)*64); }
        mma_tile8(Ab[cur], Bb[cur], acc, wr, wc, g, tig);
        if (i < nk - 1) {
            sts4_256<PA_>(Ab[cur^1], va);
            sts4_256<PB_>(Bb[cur^1], vb);
            __syncthreads();
            cur ^= 1;
        }
    }
#pragma unroll
    for (int mi = 0; mi < 2; mi++)
#pragma unroll
    for (int ni = 0; ni < 2; ni++)
#pragma unroll
    for (int e = 0; e < 4; e++)
        C[(size_t)(bm + ACC_ROW(mi, e))*N + bn + ACC_COL(ni, e)] = acc[mi][ni][e];
}

// ---------------- conv + SiLU + per-head L2 norm ----------------------------------
__global__ void conv_norm_kernel(const float* __restrict__ conv_w)
{
    int t = blockIdx.x;
    int c = threadIdx.x;
    float x0  = g_wpre[t*DMM + c];
    float xm1 = (t >= 1) ? g_wpre[(t-1)*DMM + c] : 0.f;
    float xm2 = (t >= 2) ? g_wpre[(t-2)*DMM + c] : 0.f;
    float y = conv_w[c*3+0]*xm2 + conv_w[c*3+1]*xm1 + conv_w[c*3+2]*x0;
    y = y / (1.f + expf(-y));
    float y2 = y * y;
#pragma unroll
    for (int o = 16; o; o >>= 1) y2 += __shfl_xor_sync(0xffffffffu, y2, o);
    __shared__ float wsum[32];
    if ((c & 31) == 0) wsum[c >> 5] = y2;
    __syncthreads();
    int h = c >> 6;
    float ss = wsum[2*h] + wsum[2*h+1];
    g_w[t*DMM + c] = y * rsqrtf(ss + 1e-6f);
}

// ---------------- merged: diag Md/MkD + unit-lower inversion -----------------------
// inversion: 4 threads per column, UNIFORM outer loop (all lanes iterate r=1..63)
// so warp shuffles are always converged; __syncwarp for smem visibility.
__global__ __launch_bounds__(256) void diaginv_kernel()
{
    __shared__ float Aw[64][PA_];
    __shared__ float Bk[64][PA_];
    __shared__ float L[64][65];
    __shared__ float X[64][65];
    int J = blockIdx.x, h = blockIdx.y;
    WARP_IDX;
    {
        int t = tid * 4;
#pragma unroll
        for (int u = 0; u < 4; u++) {
            int l = t + u*1024, r = l >> 6, c = l & 63;
            *(float4*)&Aw[r][c] = tf4(*(const float4*)&g_w[(size_t)(J*64 + r)*DMM + h*64 + c]);
            *(float4*)&Bk[r][c] = tf4(*(const float4*)&g_k[(size_t)(J*64 + r)*DMM + h*64 + c]);
        }
    }
    __syncthreads();
    float am[2][2][4] = {}, amk[2][2][4] = {};
    mma_tile2r(Aw, Aw, Bk, am, amk, wr, wc, g, tig);
    size_t ofs = ((size_t)h*NT + J)*4096;
#pragma unroll
    for (int mi = 0; mi < 2; mi++)
#pragma unroll
    for (int ni = 0; ni < 2; ni++)
#pragma unroll
    for (int e = 0; e < 4; e += 2) {
        int r = ACC_ROW(mi, e), c = ACC_COL(ni, e);
        float be = g_beta[(size_t)(J*64 + r)*HH + h];
        L[r][c]   = (r > c    ) ? be*am[mi][ni][e]   : (r == c     ? 1.f : 0.f);
        L[r][c+1] = (r > c + 1) ? be*am[mi][ni][e+1] : (r == c + 1 ? 1.f : 0.f);
        X[r][c]   = (r == c    ) ? 1.f : 0.f;
        X[r][c+1] = (r == c + 1) ? 1.f : 0.f;
        float2 mk;
        mk.x = (r > c    ) ? -be*amk[mi][ni][e]   : 0.f;
        mk.y = (r > c + 1) ? -be*amk[mi][ni][e+1] : 0.f;
        *(float2*)&g_MkD[ofs + r*64 + c] = mk;
    }
    __syncthreads();
    {
        int c = tid >> 2, part = tid & 3;
        for (int r = 1; r < 64; r++) {          // uniform across all lanes
            float a = 0.f;
            for (int s = c + part; s < r; s += 4)   // empty when c >= r
                a += L[r][s] * X[s][c];
            a += __shfl_xor_sync(0xffffffffu, a, 1);
            a += __shfl_xor_sync(0xffffffffu, a, 2);
            if (r > c) X[r][c] = -a;            // all 4 lanes write same value
            __syncwarp();
        }
    }
    __syncthreads();
    for (int l = tid; l < 4096; l += 256)
        g_invA[ofs + l] = X[l >> 6][l & 63];
}

// ---------------- fused row scan: Aqw/QK + solve + online softmax + PV -------------
__global__ __launch_bounds__(512) void row_kernel()
{
    extern __shared__ float sm[];
    float (*Qsm)[PA_]  = (float(*)[PA_])(sm);
    float (*Psm)[PA_]  = (float(*)[PA_])(sm + ASZ);       // Pneg state / Gf tile
    float (*Gtmp)[PA_] = (float(*)[PA_])(sm + 2*ASZ);
    float (*Wrow)[PA_] = (float(*)[PA_])(sm + 3*ASZ);     // w_J, later exp tile
    float (*Krow)[PA_] = (float(*)[PA_])(sm + 4*ASZ);     // k_J
    float (*Binv)[PB_] = (float(*)[PB_])(sm + 5*ASZ);
    float (*MkDs)[PB_] = (float(*)[PB_])(sm + 5*ASZ + BSZ);
    float (*BWn)[PB_]  = (float(*)[PB_])(sm + 5*ASZ + 2*BSZ);  // -beta*w_J
    float (*Vsm)[PB_]  = (float(*)[PB_])(sm + 5*ASZ + 3*BSZ);  // v_J
    __shared__ float red[64][8];
    int h = blockIdx.x;
    int I = NT - 1 - blockIdx.y;    // heavy rows launch first
    WARP_IDX16;
    int wcg = wid & 3;
    int r0 = wr + g, r1 = wr + g + 8;
    size_t hofs = (size_t)h*NT*4096;

    // stage Q_I once
    stage512f<PA_>(Qsm, &g_q[(size_t)(I*64)*DMM + h*64], DMM);

    // prefetch registers for J = I
    float4 vw[2], vk[2], vv[2], vbi[2], vmk[2];
    float vbe[2];
    {
        int t = tid * 4;
#pragma unroll
        for (int u = 0; u < 2; u++) {
            int l = t + u*2048, r = l >> 6, c = l & 63;
            vw[u] = *(const float4*)&g_w[(size_t)(I*64 + r)*DMM + h*64 + c];
            vk[u] = *(const float4*)&g_k[(size_t)(I*64 + r)*DMM + h*64 + c];
            vv[u] = *(const float4*)&g_v[(size_t)(I*64 + r)*DMM + h*64 + c];
            vbe[u] = g_beta[(size_t)(I*64 + r)*HH + h];
            vbi[u] = *(const float4*)&g_invA[hofs + (size_t)I*4096 + l];
            vmk[u] = *(const float4*)&g_MkD [hofs + (size_t)I*4096 + l];
        }
    }

    float Pn[2][4] = {};            // Pneg state
    float O[2][4]  = {};            // unnormalized output
    float m0 = -1e30f, m1 = -1e30f;
    float s0 = 0.f,    s1 = 0.f;

    for (int J = I; J >= 0; J--) {
        // ---- store staged operands from prefetch registers ----
        {
            int t = tid * 4;
#pragma unroll
            for (int u = 0; u < 2; u++) {
                int l = t + u*2048, r = l >> 6, c = l & 63;
                *(float4*)&Wrow[r][c] = tf4(vw[u]);
                float nb = -vbe[u];
                float4 w4 = make_float4(vw[u].x*nb, vw[u].y*nb, vw[u].z*nb, vw[u].w*nb);
                *(float4*)&BWn[r][c] = tf4(w4);
                *(float4*)&Krow[r][c] = tf4(vk[u]);
                *(float4*)&Vsm [r][c] = tf4(vv[u]);
            }
        }
        if (J < I) {
#pragma unroll
            for (int ni = 0; ni < 2; ni++) {
                int c0 = wc + ni*8 + tig*2;
                Psm[r0][c0]   = to_tf32(Pn[ni][0]);
                Psm[r0][c0+1] = to_tf32(Pn[ni][1]);
                Psm[r1][c0]   = to_tf32(Pn[ni][2]);
                Psm[r1][c0+1] = to_tf32(Pn[ni][3]);
            }
        }
        __syncthreads();

        // acc = Q@W^T (+ Pneg@W^T), sacc = Q@K^T (+ Pneg@K^T)
        float acc[2][4] = {}, sacc[2][4] = {};
        mma_tile16r(Qsm, Wrow, acc,  wr, wc, g, tig);
        mma_tile16r(Qsm, Krow, sacc, wr, wc, g, tig);
        if (J < I) {
            mma_tile16r(Psm, Wrow, acc,  wr, wc, g, tig);
            mma_tile16r(Psm, Krow, sacc, wr, wc, g, tig);
        } else {
#pragma unroll
            for (int ni = 0; ni < 2; ni++) {
                int c0 = wc + ni*8 + tig*2;
                if (c0     > r0) acc[ni][0] = 0.f;
                if (c0 + 1 > r0) acc[ni][1] = 0.f;
                if (c0     > r1) acc[ni][2] = 0.f;
                if (c0 + 1 > r1) acc[ni][3] = 0.f;
            }
        }
        // store Binv/MkD (prefetched) + Gtmp
        st512r<PB_>(Binv, vbi);
        st512r<PB_>(MkDs, vmk);
#pragma unroll
        for (int ni = 0; ni < 2; ni++) {
            int c0 = wc + ni*8 + tig*2;
            Gtmp[r0][c0]   = to_tf32(acc[ni][0]);
            Gtmp[r0][c0+1] = to_tf32(acc[ni][1]);
            Gtmp[r1][c0]   = to_tf32(acc[ni][2]);
            Gtmp[r1][c0+1] = to_tf32(acc[ni][3]);
        }
        __syncthreads();

        // prefetch next J's operands (latency hidden behind remaining MMAs)
        if (J > 0) {
            int Jn = J - 1;
            int t = tid * 4;
#pragma unroll
            for (int u = 0; u < 2; u++) {
                int l = t + u*2048, r = l >> 6, c = l & 63;
                vw[u] = *(const float4*)&g_w[(size_t)(Jn*64 + r)*DMM + h*64 + c];
                vk[u] = *(const float4*)&g_k[(size_t)(Jn*64 + r)*DMM + h*64 + c];
                vv[u] = *(const float4*)&g_v[(size_t)(Jn*64 + r)*DMM + h*64 + c];
                vbe[u] = g_beta[(size_t)(Jn*64 + r)*HH + h];
                vbi[u] = *(const float4*)&g_invA[hofs + (size_t)Jn*4096 + l];
                vmk[u] = *(const float4*)&g_MkD [hofs + (size_t)Jn*4096 + l];
            }
        }

        float Gf[2][4] = {};
        mma_tile16(Gtmp, Binv, Gf, wr, wc, g, tig);
        // write Gf into Psm (safe: all Psm readers passed the previous sync)
#pragma unroll
        for (int ni = 0; ni < 2; ni++) {
            int c0 = wc + ni*8 + tig*2;
            Psm[r0][c0]   = to_tf32(Gf[ni][0]);
            Psm[r0][c0+1] = to_tf32(Gf[ni][1]);
            Psm[r1][c0]   = to_tf32(Gf[ni][2]);
            Psm[r1][c0+1] = to_tf32(Gf[ni][3]);
        }
        __syncthreads();
        mma_tile16(Psm, MkDs, sacc, wr, wc, g, tig);   // sacc -= G@MkD (preneg)
        mma_tile16(Psm, BWn,  Pn,   wr, wc, g, tig);   // Pneg -= G@BW

        // ---- online softmax ----
        float tv[2][4];
        float lm0 = -1e30f, lm1 = -1e30f;
#pragma unroll
        for (int ni = 0; ni < 2; ni++) {
            int c0 = wc + ni*8 + tig*2;
#pragma unroll
            for (int e = 0; e < 4; e++) {
                float v = sacc[ni][e] * SCALE;
                int rr = (e < 2) ? r0 : r1;
                int cc = c0 + (e & 1);
                if (J == I && cc > rr) v = -1e30f;
                tv[ni][e] = v;
                if (e < 2) lm0 = fmaxf(lm0, v); else lm1 = fmaxf(lm1, v);
            }
        }
#pragma unroll
        for (int o = 1; o < 4; o <<= 1) {
            lm0 = fmaxf(lm0, __shfl_xor_sync(0xffffffffu, lm0, o));
            lm1 = fmaxf(lm1, __shfl_xor_sync(0xffffffffu, lm1, o));
        }
        if (tig == 0) { red[r0][wcg] = lm0; red[r1][wcg] = lm1; }
        __syncthreads();
        float m0n = fmaxf(m0, fmaxf(fmaxf(red[r0][0], red[r0][1]),
                                    fmaxf(red[r0][2], red[r0][3])));
        float m1n = fmaxf(m1, fmaxf(fmaxf(red[r1][0], red[r1][1]),
                                    fmaxf(red[r1][2], red[r1][3])));
        float sc0 = __expf(m0 - m0n), sc1 = __expf(m1 - m1n);
        m0 = m0n; m1 = m1n;
        s0 *= sc0; s1 *= sc1;
#pragma unroll
        for (int ni = 0; ni < 2; ni++)
#pragma unroll
        for (int e = 0; e < 4; e++)
            O[ni][e] *= (e < 2) ? sc0 : sc1;

        float ls0 = 0.f, ls1 = 0.f;
#pragma unroll
        for (int ni = 0; ni < 2; ni++) {
            int c0 = wc + ni*8 + tig*2;
#pragma unroll
            for (int e = 0; e < 4; e++) {
                float p = __expf(tv[ni][e] - ((e < 2) ? m0 : m1));
                if (e < 2) ls0 += p; else ls1 += p;
                int rr = (e < 2) ? r0 : r1;
                Wrow[rr][c0 + (e & 1)] = to_tf32(p);
            }
        }
#pragma unroll
        for (int o = 1; o < 4; o <<= 1) {
            ls0 += __shfl_xor_sync(0xffffffffu, ls0, o);
            ls1 += __shfl_xor_sync(0xffffffffu, ls1, o);
        }
        if (tig == 0) { red[r0][4 + wcg] = ls0; red[r1][4 + wcg] = ls1; }
        __syncthreads();
        s0 += red[r0][4] + red[r0][5] + red[r0][6] + red[r0][7];
        s1 += red[r1][4] + red[r1][5] + red[r1][6] + red[r1][7];

        mma_tile16(Wrow, Vsm, O, wr, wc, g, tig);       // O += exp(P) @ V_J
        __syncthreads();
    }

    float i0 = 1.f / s0, i1 = 1.f / s1;
#pragma unroll
    for (int ni = 0; ni < 2; ni++) {
        int c0 = wc + ni*8 + tig*2;
        float2 v0 = make_float2(O[ni][0]*i0, O[ni][1]*i0);
        float2 v1 = make_float2(O[ni][2]*i1, O[ni][3]*i1);
        *(float2*)&g_o[(size_t)(I*64 + r0)*DMM + h*64 + c0] = v0;
        *(float2*)&g_o[(size_t)(I*64 + r1)*DMM + h*64 + c0] = v1;
    }
}

// ---------------- launcher ----------------------------------------------------------
extern "C" void kernel_launch(void* const* d_in, const int* in_sizes, int n_in,
                              void* d_out, int out_size)
{
    const float* x     = (const float*)d_in[0];
    const float* Wq    = (const float*)d_in[1];
    const float* Wk    = (const float*)d_in[2];
    const float* Wv    = (const float*)d_in[3];
    const float* Ww1   = (const float*)d_in[4];
    const float* Ww2   = (const float*)d_in[5];
    const float* convw = (const float*)d_in[6];
    const float* Wb    = (const float*)d_in[7];
    const float* Wo    = (const float*)d_in[8];

    float *xw1, *wpre, *o;
    cudaGetSymbolAddress((void**)&xw1,  g_xw1);
    cudaGetSymbolAddress((void**)&wpre, g_wpre);
    cudaGetSymbolAddress((void**)&o,    g_o);

    const int SM_DB  = (2*ASZ + 2*BSZ) * 4;     // 71680 B
    const int SM_ROW = (5*ASZ + 4*BSZ) * 4;     // 160768 B
    static bool attr_set = false;
    if (!attr_set) {
        cudaFuncSetAttribute(proj_kernel, cudaFuncAttributeMaxDynamicSharedMemorySize, SM_DB);
        cudaFuncSetAttribute(gemm_tc,     cudaFuncAttributeMaxDynamicSharedMemorySize, SM_DB);
        cudaFuncSetAttribute(row_kernel,  cudaFuncAttributeMaxDynamicSharedMemorySize, SM_ROW);
        attr_set = true;
    }

    dim3 blk(256);

    proj_kernel<<<dim3((NPROJ + 63)/64, 16), blk, SM_DB>>>(x, Wq, Wk, Wv, Ww1, Wb);
    gemm_tc<<<dim3(16, 16), blk, SM_DB>>>(xw1, Ww2, wpre, DMM, RNK);
    conv_norm_kernel<<<TT, 1024>>>(convw);
    diaginv_kernel<<<dim3(NT, HH), blk>>>();
    row_kernel<<<dim3(HH, NT), 512, SM_ROW>>>();
    gemm_tc<<<dim3(16, 16), blk, SM_DB>>>(o, Wo, (float*)d_out, DMM, DMM);
}